// round 3
// baseline (speedup 1.0000x reference)
#include <cuda_runtime.h>
#include <cuda_bf16.h>
#include <math.h>

// Problem constants
#define BATCH 8
#define SEQ   1024
#define DMODEL 1024
#define NHEADS 16
#define DK    64
#define NREL  257          // 2*128+1
#define MAXREL 128
#define MTOT  (BATCH*SEQ)  // 8192
#define BH    (BATCH*NHEADS) // 128

// Scratch (device globals — allocation-free rule)
__device__ float g_Q[BH*SEQ*DK];        // [B,H,S,dk]
__device__ float g_K[BH*SEQ*DK];
__device__ float g_V[BH*SEQ*DK];
__device__ float g_Qrel[BH*SEQ*NREL];
__device__ float g_ctx[MTOT*DMODEL];    // [B,S,D]

// ---------------------------------------------------------------------------
// GEMM: C[m,n] = sum_k A[m,k]*W[n,k]  (A: [8192,1024] rm, W: [1024,1024] rm)
// MODE 0: write to projection layout [B,H,S,dk]; MODE 1: plain row-major + bias
// ---------------------------------------------------------------------------
template<int MODE>
__global__ __launch_bounds__(256) void gemm128(const float* __restrict__ A,
                                               const float* __restrict__ W,
                                               const float* __restrict__ bias,
                                               float* __restrict__ out) {
    __shared__ float As[16][132];
    __shared__ float Bs[16][132];
    const int tid = threadIdx.x;
    const int bm = blockIdx.y * 128, bn = blockIdx.x * 128;
    const int tx = tid & 15, ty = tid >> 4;
    const int lr = tid >> 2, lc = (tid & 3) * 4;

    float acc[8][8];
#pragma unroll
    for (int i = 0; i < 8; i++)
#pragma unroll
        for (int j = 0; j < 8; j++) acc[i][j] = 0.f;

    const float* Ap = A + (size_t)(bm + lr) * DMODEL + lc;
    const float* Wp = W + (size_t)(bn + lr) * DMODEL + lc;

    for (int k0 = 0; k0 < DMODEL; k0 += 16) {
        float4 a0 = *(const float4*)(Ap + k0);
        float4 a1 = *(const float4*)(Ap + (size_t)64 * DMODEL + k0);
        float4 b0 = *(const float4*)(Wp + k0);
        float4 b1 = *(const float4*)(Wp + (size_t)64 * DMODEL + k0);
        As[lc + 0][lr] = a0.x; As[lc + 1][lr] = a0.y; As[lc + 2][lr] = a0.z; As[lc + 3][lr] = a0.w;
        As[lc + 0][lr + 64] = a1.x; As[lc + 1][lr + 64] = a1.y; As[lc + 2][lr + 64] = a1.z; As[lc + 3][lr + 64] = a1.w;
        Bs[lc + 0][lr] = b0.x; Bs[lc + 1][lr] = b0.y; Bs[lc + 2][lr] = b0.z; Bs[lc + 3][lr] = b0.w;
        Bs[lc + 0][lr + 64] = b1.x; Bs[lc + 1][lr + 64] = b1.y; Bs[lc + 2][lr + 64] = b1.z; Bs[lc + 3][lr + 64] = b1.w;
        __syncthreads();
#pragma unroll
        for (int k = 0; k < 16; k++) {
            float ar[8], br[8];
            *(float4*)(ar)     = *(float4*)&As[k][ty * 8];
            *(float4*)(ar + 4) = *(float4*)&As[k][ty * 8 + 4];
            *(float4*)(br)     = *(float4*)&Bs[k][tx * 8];
            *(float4*)(br + 4) = *(float4*)&Bs[k][tx * 8 + 4];
#pragma unroll
            for (int i = 0; i < 8; i++)
#pragma unroll
                for (int j = 0; j < 8; j++) acc[i][j] += ar[i] * br[j];
        }
        __syncthreads();
    }

#pragma unroll
    for (int i = 0; i < 8; i++) {
        const int m = bm + ty * 8 + i;
#pragma unroll
        for (int j = 0; j < 8; j++) {
            const int n = bn + tx * 8 + j;
            float v = acc[i][j];
            if (MODE == 0) {
                const int b = m >> 10, s = m & 1023, h = n >> 6, d = n & 63;
                out[(((size_t)(b * NHEADS + h) << 10) + s) * DK + d] = v;
            } else {
                out[(size_t)m * DMODEL + n] = v + bias[n];
            }
        }
    }
}

// ---------------------------------------------------------------------------
// Qrel[bh,l,p] = sum_d Q[bh,l,d] * rel_k[p,d]
// ---------------------------------------------------------------------------
__global__ __launch_bounds__(256) void qrel_kernel(const float* __restrict__ Qg,
                                                   const float* __restrict__ relk,
                                                   float* __restrict__ Qrel) {
    __shared__ float Qs[64][65];
    __shared__ float Rs[64][65];
    const int tid = threadIdx.x;
    const int p0 = blockIdx.x * 64, l0 = blockIdx.y * 64, bh = blockIdx.z;
#pragma unroll
    for (int i = 0; i < 16; i++) {
        const int lin = tid + i * 256;
        const int row = lin >> 6, col = lin & 63;
        Qs[row][col] = Qg[((size_t)((bh << 10) + l0 + row)) * DK + col];
        const int p = p0 + row;
        Rs[row][col] = (p < NREL) ? relk[p * DK + col] : 0.f;
    }
    __syncthreads();
    const int tx = tid & 15, ty = tid >> 4;
    float acc[4][4];
#pragma unroll
    for (int i = 0; i < 4; i++)
#pragma unroll
        for (int j = 0; j < 4; j++) acc[i][j] = 0.f;
#pragma unroll 8
    for (int k = 0; k < 64; k++) {
        float q[4], rv[4];
#pragma unroll
        for (int i = 0; i < 4; i++) q[i] = Qs[ty * 4 + i][k];
#pragma unroll
        for (int j = 0; j < 4; j++) rv[j] = Rs[tx * 4 + j][k];
#pragma unroll
        for (int i = 0; i < 4; i++)
#pragma unroll
            for (int j = 0; j < 4; j++) acc[i][j] += q[i] * rv[j];
    }
#pragma unroll
    for (int i = 0; i < 4; i++) {
        const int l = l0 + ty * 4 + i;
#pragma unroll
        for (int j = 0; j < 4; j++) {
            const int p = p0 + tx * 4 + j;
            if (p < NREL)
                Qrel[((size_t)((bh << 10) + l)) * NREL + p] = acc[i][j];
        }
    }
}

// ---------------------------------------------------------------------------
// Scores + rel-pos bias + temporal decay + softmax -> attn (written to d_out)
// One block: 16 query rows x full 1024 keys; row buffer in smem (dynamic)
// ---------------------------------------------------------------------------
#define ATTN_SMEM_FLOATS (16*1024 + 16*64 + 64*65 + 256 + 16 + 16)
__global__ __launch_bounds__(256) void attn_kernel(const float* __restrict__ Qg,
                                                   const float* __restrict__ Kg,
                                                   const float* __restrict__ Qrel,
                                                   const float* __restrict__ decay,
                                                   float* __restrict__ attn) {
    extern __shared__ float sm[];
    float* sbuf = sm;                 // [16][1024]
    float* Qs   = sm + 16 * 1024;     // [16][64]
    float* Ks   = Qs + 16 * 64;       // [64][65]
    float* red  = Ks + 64 * 65;       // [16][16]
    float* rowm = red + 256;          // [16]
    float* rows = rowm + 16;          // [16]

    const int tid = threadIdx.x;
    const int bh = blockIdx.y;
    const int h  = bh & 15;
    const int l0 = blockIdx.x * 16;
    const float dh = decay[h];

#pragma unroll
    for (int i = 0; i < 4; i++) {
        const int lin = tid + i * 256;
        const int row = lin >> 6, col = lin & 63;
        Qs[row * 64 + col] = Qg[((size_t)((bh << 10) + l0 + row)) * DK + col];
    }
    const int tx = tid & 63, tg = tid >> 6;

    for (int rc = 0; rc < 16; rc++) {
        // load full 64x64 K chunk (4096 elements -> 16 iterations of 256)
#pragma unroll
        for (int i = 0; i < 16; i++) {
            const int lin = tid + i * 256;
            const int row = lin >> 6, col = lin & 63;
            Ks[row * 65 + col] = Kg[((size_t)((bh << 10) + (rc << 6) + row)) * DK + col];
        }
        __syncthreads();
        float s0 = 0.f, s1 = 0.f, s2 = 0.f, s3 = 0.f;
#pragma unroll 8
        for (int k = 0; k < 64; k++) {
            const float kv = Ks[tx * 65 + k];
            s0 += Qs[(tg)      * 64 + k] * kv;
            s1 += Qs[(tg + 4)  * 64 + k] * kv;
            s2 += Qs[(tg + 8)  * 64 + k] * kv;
            s3 += Qs[(tg + 12) * 64 + k] * kv;
        }
        const int r = (rc << 6) + tx;
        float sv[4] = {s0, s1, s2, s3};
#pragma unroll
        for (int i = 0; i < 4; i++) {
            const int lrow = tg + 4 * i;
            const int lg = l0 + lrow;
            const int rel = r - lg;
            const int relc = rel < -MAXREL ? -MAXREL : (rel > MAXREL ? MAXREL : rel);
            float sc = sv[i] * 0.125f
                     + Qrel[((size_t)((bh << 10) + lg)) * NREL + relc + MAXREL]
                     - dh * fabsf((float)rel);
            sbuf[lrow * 1024 + r] = sc;
        }
        __syncthreads();
    }

    // softmax over 1024 cols per row; 16 threads per row
    const int row = tid >> 4, lane = tid & 15;
    float m = -3.0e38f;
    for (int j = 0; j < 64; j++) m = fmaxf(m, sbuf[row * 1024 + lane + (j << 4)]);
    red[row * 16 + lane] = m;
    __syncthreads();
    if (lane == 0) {
        float mm = red[row * 16];
        for (int j = 1; j < 16; j++) mm = fmaxf(mm, red[row * 16 + j]);
        rowm[row] = mm;
    }
    __syncthreads();
    const float mm = rowm[row];
    float sum = 0.f;
    for (int j = 0; j < 64; j++) {
        const int c = lane + (j << 4);
        const float e = __expf(sbuf[row * 1024 + c] - mm);
        sbuf[row * 1024 + c] = e;
        sum += e;
    }
    red[row * 16 + lane] = sum;
    __syncthreads();
    if (lane == 0) {
        float ss = 0.f;
        for (int j = 0; j < 16; j++) ss += red[row * 16 + j];
        rows[row] = ss;
    }
    __syncthreads();

    for (int l = 0; l < 16; l++) {
        const float inv = 1.0f / rows[l];
        float* dst = attn + (((size_t)(bh << 10) + l0 + l) << 10);
#pragma unroll
        for (int j = 0; j < 4; j++) {
            const int c = tid + (j << 8);
            dst[c] = sbuf[l * 1024 + c] * inv;
        }
    }
}

// ---------------------------------------------------------------------------
// Context: ctx[b,l,h*64+d] = sum_r attn*V  +  sum_p agg[l,p]*rel_v[p,d]
// agg[l,p] = sum over r mapping to relative bucket p
// ---------------------------------------------------------------------------
__global__ __launch_bounds__(256) void ctx_kernel(const float* __restrict__ attn,
                                                  const float* __restrict__ Vg,
                                                  const float* __restrict__ relv,
                                                  float* __restrict__ ctx) {
    __shared__ float At[16][80];
    __shared__ float Vs[64][65];
    __shared__ float aggs[16][NREL];

    const int tid = threadIdx.x;
    const int bh = blockIdx.y, b = bh >> 4, h = bh & 15;
    const int l0 = blockIdx.x * 16;

    for (int i = tid; i < 16 * NREL; i += 256) (&aggs[0][0])[i] = 0.f;
    __syncthreads();

    const int d = tid & 63, lg4 = tid >> 6;
    const int row = tid >> 4, lane = tid & 15;
    float acc[4] = {0.f, 0.f, 0.f, 0.f};
    float c0 = 0.f, c1 = 0.f;

    for (int rc = 0; rc < 16; rc++) {
#pragma unroll
        for (int i = 0; i < 4; i++) {
            const int lin = tid + i * 256;
            const int ar = lin >> 6, ac = lin & 63;
            At[ar][ac] = attn[(((size_t)(bh << 10) + l0 + ar) << 10) + (rc << 6) + ac];
        }
#pragma unroll
        for (int i = 0; i < 16; i++) {
            const int lin = tid + i * 256;
            const int vr = lin >> 6, vc = lin & 63;
            Vs[vr][vc] = Vg[((size_t)((bh << 10) + (rc << 6) + vr)) * DK + vc];
        }
        __syncthreads();
#pragma unroll 8
        for (int rr = 0; rr < 64; rr++) {
            const float vv = Vs[rr][d];
            acc[0] += At[lg4][rr] * vv;
            acc[1] += At[lg4 + 4][rr] * vv;
            acc[2] += At[lg4 + 8][rr] * vv;
            acc[3] += At[lg4 + 12][rr] * vv;
        }
#pragma unroll
        for (int jj = 0; jj < 4; jj++) {
            const int rr = lane + (jj << 4);
            const int r = (rc << 6) + rr;
            const float a = At[row][rr];
            const int rel = r - (l0 + row);
            if (rel <= -MAXREL)      c0 += a;
            else if (rel >= MAXREL)  c1 += a;
            else                     aggs[row][rel + MAXREL] = a;  // unique writer
        }
        __syncthreads();
    }
    atomicAdd(&aggs[row][0], c0);
    atomicAdd(&aggs[row][NREL - 1], c1);
    __syncthreads();

    for (int p0 = 0; p0 < NREL; p0 += 64) {
        const int cnt = (NREL - p0) < 64 ? (NREL - p0) : 64;
#pragma unroll
        for (int i = 0; i < 16; i++) {
            const int lin = tid + i * 256;
            const int vr = lin >> 6, vc = lin & 63;
            Vs[vr][vc] = (vr < cnt) ? relv[(p0 + vr) * DK + vc] : 0.f;
        }
        __syncthreads();
        for (int pp = 0; pp < cnt; pp++) {
            const float rv = Vs[pp][d];
            acc[0] += aggs[lg4][p0 + pp] * rv;
            acc[1] += aggs[lg4 + 4][p0 + pp] * rv;
            acc[2] += aggs[lg4 + 8][p0 + pp] * rv;
            acc[3] += aggs[lg4 + 12][p0 + pp] * rv;
        }
        __syncthreads();
    }

#pragma unroll
    for (int i = 0; i < 4; i++) {
        const int lg = l0 + lg4 + 4 * i;
        ctx[(((size_t)(b << 10) + lg) << 10) + (h << 6) + d] = acc[i];
    }
}

// ---------------------------------------------------------------------------
extern "C" void kernel_launch(void* const* d_in, const int* in_sizes, int n_in,
                              void* d_out, int out_size) {
    const float* query = (const float*)d_in[0];
    const float* key_  = (const float*)d_in[1];
    const float* value = (const float*)d_in[2];
    const float* w_q   = (const float*)d_in[3];
    const float* w_k   = (const float*)d_in[4];
    const float* w_v   = (const float*)d_in[5];
    const float* w_o   = (const float*)d_in[6];
    const float* b_o   = (const float*)d_in[7];
    const float* rel_k = (const float*)d_in[8];
    const float* rel_v = (const float*)d_in[9];
    const float* decay = (const float*)d_in[10];

    float* out  = (float*)d_out;                     // [B,S,D]
    float* attn = out + (size_t)MTOT * DMODEL;       // [B,H,S,S]

    float *Q, *K, *V, *Qrel, *ctx;
    cudaGetSymbolAddress((void**)&Q,    g_Q);
    cudaGetSymbolAddress((void**)&K,    g_K);
    cudaGetSymbolAddress((void**)&V,    g_V);
    cudaGetSymbolAddress((void**)&Qrel, g_Qrel);
    cudaGetSymbolAddress((void**)&ctx,  g_ctx);

    dim3 gg(DMODEL / 128, MTOT / 128);  // (8, 64)
    gemm128<0><<<gg, 256>>>(query, w_q, nullptr, Q);
    gemm128<0><<<gg, 256>>>(key_,  w_k, nullptr, K);
    gemm128<0><<<gg, 256>>>(value, w_v, nullptr, V);

    qrel_kernel<<<dim3(5, 16, BH), 256>>>(Q, rel_k, Qrel);

    static const size_t attn_smem = ATTN_SMEM_FLOATS * sizeof(float);
    cudaFuncSetAttribute(attn_kernel, cudaFuncAttributeMaxDynamicSharedMemorySize,
                         (int)attn_smem);
    attn_kernel<<<dim3(SEQ / 16, BH), 256, attn_smem>>>(Q, K, Qrel, decay, attn);

    ctx_kernel<<<dim3(SEQ / 16, BH), 256>>>(attn, V, rel_v, ctx);

    gemm128<1><<<gg, 256>>>(ctx, w_o, b_o, out);
}

// round 5
// speedup vs baseline: 1.3524x; 1.3524x over previous
#include <cuda_runtime.h>
#include <cuda_bf16.h>
#include <math.h>
#include <stdint.h>

#define BATCH 8
#define SEQ   1024
#define DMODEL 1024
#define NHEADS 16
#define DK    64
#define NREL  257
#define MAXREL 128
#define MTOT  (BATCH*SEQ)
#define BH    (BATCH*NHEADS)

__device__ float g_Q[BH*SEQ*DK];
__device__ float g_K[BH*SEQ*DK];
__device__ float g_V[BH*SEQ*DK];
__device__ float g_Qrel[BH*SEQ*NREL];
__device__ float g_ctx[MTOT*DMODEL];
__device__ __nv_bfloat16 g_Ah[MTOT*DMODEL];
__device__ __nv_bfloat16 g_Al[MTOT*DMODEL];
__device__ __nv_bfloat16 g_Wh[DMODEL*DMODEL];
__device__ __nv_bfloat16 g_Wl[DMODEL*DMODEL];

// ---------------- helpers ----------------
__device__ __forceinline__ uint32_t s2u(const void* p) {
    uint32_t a;
    asm("{ .reg .u64 t; cvta.to.shared.u64 t, %1; cvt.u32.u64 %0, t; }" : "=r"(a) : "l"(p));
    return a;
}
__device__ __forceinline__ void cp16(uint32_t dst, const void* src) {
    asm volatile("cp.async.cg.shared.global [%0], [%1], 16;" :: "r"(dst), "l"(src) : "memory");
}
__device__ __forceinline__ void ldm4(uint32_t* r, uint32_t addr) {
    asm volatile("ldmatrix.sync.aligned.m8n8.x4.shared.b16 {%0,%1,%2,%3}, [%4];"
                 : "=r"(r[0]), "=r"(r[1]), "=r"(r[2]), "=r"(r[3]) : "r"(addr));
}
__device__ __forceinline__ void mma16816(float* d, const uint32_t* a, const uint32_t* b) {
    asm volatile(
        "mma.sync.aligned.m16n8k16.row.col.f32.bf16.bf16.f32 "
        "{%0,%1,%2,%3}, {%4,%5,%6,%7}, {%8,%9}, {%0,%1,%2,%3};"
        : "+f"(d[0]), "+f"(d[1]), "+f"(d[2]), "+f"(d[3])
        : "r"(a[0]), "r"(a[1]), "r"(a[2]), "r"(a[3]), "r"(b[0]), "r"(b[1]));
}

// ---------------- fp32 -> bf16 hi/lo split ----------------
__global__ __launch_bounds__(256) void cvt_split(const float4* __restrict__ x,
                                                 uint2* __restrict__ hi,
                                                 uint2* __restrict__ lo) {
    const int i = blockIdx.x * 256 + threadIdx.x;
    const float4 v = x[i];
    __nv_bfloat16 h0 = __float2bfloat16(v.x), h1 = __float2bfloat16(v.y);
    __nv_bfloat16 h2 = __float2bfloat16(v.z), h3 = __float2bfloat16(v.w);
    __nv_bfloat16 l0 = __float2bfloat16(v.x - __bfloat162float(h0));
    __nv_bfloat16 l1 = __float2bfloat16(v.y - __bfloat162float(h1));
    __nv_bfloat16 l2 = __float2bfloat16(v.z - __bfloat162float(h2));
    __nv_bfloat16 l3 = __float2bfloat16(v.w - __bfloat162float(h3));
    uint2 H, L;
    H.x = (uint32_t)__bfloat16_as_ushort(h0) | ((uint32_t)__bfloat16_as_ushort(h1) << 16);
    H.y = (uint32_t)__bfloat16_as_ushort(h2) | ((uint32_t)__bfloat16_as_ushort(h3) << 16);
    L.x = (uint32_t)__bfloat16_as_ushort(l0) | ((uint32_t)__bfloat16_as_ushort(l1) << 16);
    L.y = (uint32_t)__bfloat16_as_ushort(l2) | ((uint32_t)__bfloat16_as_ushort(l3) << 16);
    hi[i] = H;
    lo[i] = L;
}

// ---------------- mma.sync bf16 split GEMM ----------------
// C[m,n] = sum_k A[m,k]*W[n,k], A=Ah+Al, W=Wh+Wl (3 terms, fp32 reg accum)
// Block 128x128, BK=64, cp.async double buffer, 8 warps (2x4), warp tile 64x32.
#define PITCH 72                       // bf16 per smem row (64 + 8 pad)
#define MATB (128*PITCH*2)             // 18432 bytes per matrix per stage
#define STAGEB (4*MATB)                // Ah|Al|Wh|Wl = 73728 bytes
#define GEMM_SMEM (2*STAGEB)           // 147456

template<int MODE>
__global__ __launch_bounds__(256, 1) void gemm_mma(const __nv_bfloat16* __restrict__ Ah,
                                                   const __nv_bfloat16* __restrict__ Al,
                                                   const __nv_bfloat16* __restrict__ Wh,
                                                   const __nv_bfloat16* __restrict__ Wl,
                                                   const float* __restrict__ bias,
                                                   float* __restrict__ out) {
    extern __shared__ char smc[];
    const uint32_t sb = s2u(smc);
    const int tid = threadIdx.x, wid = tid >> 5, lane = tid & 31;
    const int m0 = blockIdx.y * 128, n0 = blockIdx.x * 128;
    const int wm = wid >> 2, wn = wid & 3;

    float acc[4][4][4];
#pragma unroll
    for (int i = 0; i < 4; i++)
#pragma unroll
        for (int j = 0; j < 4; j++)
#pragma unroll
            for (int q = 0; q < 4; q++) acc[i][j][q] = 0.f;

    // stage issue: 1024 16B-chunks per matrix, 4 matrices, 256 threads
    auto issue = [&](int s) {
        const uint32_t bu = sb + (s & 1) * STAGEB;
        const int k0 = s * 64;
#pragma unroll
        for (int it = 0; it < 4; it++) {
            const int idx = tid + it * 256;
            const int row = idx >> 3, j = idx & 7;
            const uint32_t doff = row * (PITCH * 2) + j * 16;
            const size_t ga = ((size_t)(m0 + row) * 1024 + k0 + j * 8) * 2;
            const size_t gw = ((size_t)(n0 + row) * 1024 + k0 + j * 8) * 2;
            cp16(bu + 0 * MATB + doff, (const char*)Ah + ga);
            cp16(bu + 1 * MATB + doff, (const char*)Al + ga);
            cp16(bu + 2 * MATB + doff, (const char*)Wh + gw);
            cp16(bu + 3 * MATB + doff, (const char*)Wl + gw);
        }
        asm volatile("cp.async.commit_group;" ::: "memory");
    };

    issue(0);
    for (int s = 0; s < 16; s++) {
        if (s + 1 < 16) {
            issue(s + 1);
            asm volatile("cp.async.wait_group 1;" ::: "memory");
        } else {
            asm volatile("cp.async.wait_group 0;" ::: "memory");
        }
        __syncthreads();
        const uint32_t bu = sb + (s & 1) * STAGEB;
#pragma unroll
        for (int kk = 0; kk < 4; kk++) {
            const int k16 = kk * 16;
            uint32_t ah[4][4], al[4][4];
#pragma unroll
            for (int i = 0; i < 4; i++) {
                const uint32_t addr = bu +
                    ((wm * 64 + i * 16 + (lane & 15)) * PITCH + k16 + (lane >> 4) * 8) * 2;
                ldm4(ah[i], addr);
                ldm4(al[i], addr + MATB);
            }
            uint32_t wh[2][4], wl[2][4];
#pragma unroll
            for (int j = 0; j < 2; j++) {
                const int mat = lane >> 3, rr = lane & 7;
                const int n = wn * 32 + j * 16 + (mat >> 1) * 8 + rr;
                const int k = k16 + (mat & 1) * 8;
                const uint32_t addr = bu + 2 * MATB + (n * PITCH + k) * 2;
                ldm4(wh[j], addr);
                ldm4(wl[j], addr + MATB);
            }
#pragma unroll
            for (int i = 0; i < 4; i++)
#pragma unroll
                for (int nt = 0; nt < 4; nt++) {
                    const uint32_t* bhf = &wh[nt >> 1][(nt & 1) * 2];
                    const uint32_t* blf = &wl[nt >> 1][(nt & 1) * 2];
                    mma16816(acc[i][nt], ah[i], bhf);
                    mma16816(acc[i][nt], ah[i], blf);
                    mma16816(acc[i][nt], al[i], bhf);
                }
        }
        __syncthreads();
    }

    // epilogue: D frag: d0,d1 -> (row, col), (row, col+1); d2,d3 -> row+8
    const int rr = lane >> 2, cc = (lane & 3) * 2;
#pragma unroll
    for (int i = 0; i < 4; i++) {
#pragma unroll
        for (int nt = 0; nt < 4; nt++) {
            const int n = n0 + wn * 32 + nt * 8 + cc;
#pragma unroll
            for (int half = 0; half < 2; half++) {
                const int m = m0 + wm * 64 + i * 16 + rr + half * 8;
                float2 v;
                v.x = acc[i][nt][half * 2 + 0];
                v.y = acc[i][nt][half * 2 + 1];
                if (MODE == 0) {
                    const int b = m >> 10, sI = m & 1023, h = n >> 6, dd = n & 63;
                    *(float2*)(out + (((size_t)(b * NHEADS + h) << 10) + sI) * 64 + dd) = v;
                } else {
                    v.x += bias[n];
                    v.y += bias[n + 1];
                    *(float2*)(out + (size_t)m * 1024 + n) = v;
                }
            }
        }
    }
}

// ---------------- Qrel ----------------
__global__ __launch_bounds__(256) void qrel_kernel(const float* __restrict__ Qg,
                                                   const float* __restrict__ relk,
                                                   float* __restrict__ Qrel) {
    __shared__ float Qs[64][65];
    __shared__ float Rs[64][65];
    const int tid = threadIdx.x;
    const int p0 = blockIdx.x * 64, l0 = blockIdx.y * 64, bh = blockIdx.z;
#pragma unroll
    for (int i = 0; i < 16; i++) {
        const int lin = tid + i * 256;
        const int row = lin >> 6, col = lin & 63;
        Qs[row][col] = Qg[((size_t)((bh << 10) + l0 + row)) * DK + col];
        const int p = p0 + row;
        Rs[row][col] = (p < NREL) ? relk[p * DK + col] : 0.f;
    }
    __syncthreads();
    const int tx = tid & 15, ty = tid >> 4;
    float acc[4][4];
#pragma unroll
    for (int i = 0; i < 4; i++)
#pragma unroll
        for (int j = 0; j < 4; j++) acc[i][j] = 0.f;
#pragma unroll 8
    for (int k = 0; k < 64; k++) {
        float q[4], rv[4];
#pragma unroll
        for (int i = 0; i < 4; i++) q[i] = Qs[ty * 4 + i][k];
#pragma unroll
        for (int j = 0; j < 4; j++) rv[j] = Rs[tx * 4 + j][k];
#pragma unroll
        for (int i = 0; i < 4; i++)
#pragma unroll
            for (int j = 0; j < 4; j++) acc[i][j] += q[i] * rv[j];
    }
#pragma unroll
    for (int i = 0; i < 4; i++) {
        const int l = l0 + ty * 4 + i;
#pragma unroll
        for (int j = 0; j < 4; j++) {
            const int p = p0 + tx * 4 + j;
            if (p < NREL)
                Qrel[((size_t)((bh << 10) + l)) * NREL + p] = acc[i][j];
        }
    }
}

// ---------------- attn: K-in-registers QK + softmax ----------------
#define ATTN_SMEM_FLOATS (16*1024 + 16*64 + 256 + 16 + 16)
__global__ __launch_bounds__(256) void attn_kernel(const float* __restrict__ Qg,
                                                   const float* __restrict__ Kg,
                                                   const float* __restrict__ Qrel,
                                                   const float* __restrict__ decay,
                                                   float* __restrict__ attn) {
    extern __shared__ float sm[];
    float* sbuf = sm;               // [16][1024]
    float* Qs   = sm + 16 * 1024;   // [16][64]
    float* red  = Qs + 16 * 64;     // [16][16]
    float* rowm = red + 256;        // [16]
    float* rows = rowm + 16;        // [16]

    const int tid = threadIdx.x;
    const int bh = blockIdx.y;
    const int h  = bh & 15;
    const int l0 = blockIdx.x * 16;
    const float dh = decay[h];

#pragma unroll
    for (int i = 0; i < 4; i++) {
        const int lin = tid + i * 256;
        Qs[lin] = Qg[((size_t)((bh << 10) + l0 + (lin >> 6))) * DK + (lin & 63)];
    }
    __syncthreads();
    const float4* Qs4 = (const float4*)Qs;

    for (int ch = 0; ch < 4; ch++) {
        const int r = (ch << 8) + tid;
        float4 kr[16];
        const float4* kp = (const float4*)(Kg + (((size_t)(bh << 10)) + r) * 64);
#pragma unroll
        for (int i = 0; i < 16; i++) kr[i] = kp[i];
        float acc[16];
#pragma unroll
        for (int i = 0; i < 16; i++) acc[i] = 0.f;
#pragma unroll
        for (int k4 = 0; k4 < 16; k4++) {
            const float4 kv = kr[k4];
#pragma unroll
            for (int row = 0; row < 16; row++) {
                const float4 q = Qs4[row * 16 + k4];
                acc[row] = fmaf(q.x, kv.x, fmaf(q.y, kv.y,
                           fmaf(q.z, kv.z, fmaf(q.w, kv.w, acc[row]))));
            }
        }
#pragma unroll
        for (int row = 0; row < 16; row++) {
            const int lg = l0 + row;
            const int rel = r - lg;
            const int relc = rel < -MAXREL ? -MAXREL : (rel > MAXREL ? MAXREL : rel);
            const float sc = acc[row] * 0.125f
                           + __ldg(Qrel + ((size_t)((bh << 10) + lg)) * NREL + relc + MAXREL)
                           - dh * fabsf((float)rel);
            sbuf[(row << 10) + r] = sc;
        }
    }
    __syncthreads();

    const int row = tid >> 4, lane = tid & 15;
    float m = -3.0e38f;
    for (int j = 0; j < 64; j++) m = fmaxf(m, sbuf[(row << 10) + lane + (j << 4)]);
    red[row * 16 + lane] = m;
    __syncthreads();
    if (lane == 0) {
        float mm = red[row * 16];
        for (int j = 1; j < 16; j++) mm = fmaxf(mm, red[row * 16 + j]);
        rowm[row] = mm;
    }
    __syncthreads();
    const float mm = rowm[row];
    float sum = 0.f;
    for (int j = 0; j < 64; j++) {
        const int c = lane + (j << 4);
        const float e = __expf(sbuf[(row << 10) + c] - mm);
        sbuf[(row << 10) + c] = e;
        sum += e;
    }
    red[row * 16 + lane] = sum;
    __syncthreads();
    if (lane == 0) {
        float ss = 0.f;
        for (int j = 0; j < 16; j++) ss += red[row * 16 + j];
        rows[row] = ss;
    }
    __syncthreads();

    for (int l = 0; l < 16; l++) {
        const float inv = 1.0f / rows[l];
        float* dst = attn + (((size_t)(bh << 10) + l0 + l) << 10);
#pragma unroll
        for (int j = 0; j < 4; j++) {
            const int c = tid + (j << 8);
            dst[c] = sbuf[(l << 10) + c] * inv;
        }
    }
}

// ---------------- ctx ----------------
__global__ __launch_bounds__(256) void ctx_kernel(const float* __restrict__ attn,
                                                  const float* __restrict__ Vg,
                                                  const float* __restrict__ relv,
                                                  float* __restrict__ ctx) {
    __shared__ float At[16][80];
    __shared__ float Vs[64][65];
    __shared__ float aggs[16][NREL];

    const int tid = threadIdx.x;
    const int bh = blockIdx.y, b = bh >> 4, h = bh & 15;
    const int l0 = blockIdx.x * 16;

    for (int i = tid; i < 16 * NREL; i += 256) (&aggs[0][0])[i] = 0.f;
    __syncthreads();

    const int d = tid & 63, lg4 = tid >> 6;
    const int row = tid >> 4, lane = tid & 15;
    float acc[4] = {0.f, 0.f, 0.f, 0.f};
    float c0 = 0.f, c1 = 0.f;

    for (int rc = 0; rc < 16; rc++) {
#pragma unroll
        for (int i = 0; i < 4; i++) {
            const int lin = tid + i * 256;
            const int ar = lin >> 6, ac = lin & 63;
            At[ar][ac] = attn[(((size_t)(bh << 10) + l0 + ar) << 10) + (rc << 6) + ac];
        }
#pragma unroll
        for (int i = 0; i < 16; i++) {
            const int lin = tid + i * 256;
            const int vr = lin >> 6, vc = lin & 63;
            Vs[vr][vc] = Vg[((size_t)((bh << 10) + (rc << 6) + vr)) * DK + vc];
        }
        __syncthreads();
#pragma unroll 8
        for (int rr = 0; rr < 64; rr++) {
            const float vv = Vs[rr][d];
            acc[0] += At[lg4][rr] * vv;
            acc[1] += At[lg4 + 4][rr] * vv;
            acc[2] += At[lg4 + 8][rr] * vv;
            acc[3] += At[lg4 + 12][rr] * vv;
        }
#pragma unroll
        for (int jj = 0; jj < 4; jj++) {
            const int rr = lane + (jj << 4);
            const int r = (rc << 6) + rr;
            const float a = At[row][rr];
            const int rel = r - (l0 + row);
            if (rel <= -MAXREL)      c0 += a;
            else if (rel >= MAXREL)  c1 += a;
            else                     aggs[row][rel + MAXREL] = a;
        }
        __syncthreads();
    }
    atomicAdd(&aggs[row][0], c0);
    atomicAdd(&aggs[row][NREL - 1], c1);
    __syncthreads();

    for (int p0 = 0; p0 < NREL; p0 += 64) {
        const int cnt = (NREL - p0) < 64 ? (NREL - p0) : 64;
#pragma unroll
        for (int i = 0; i < 16; i++) {
            const int lin = tid + i * 256;
            const int vr = lin >> 6, vc = lin & 63;
            Vs[vr][vc] = (vr < cnt) ? relv[(p0 + vr) * DK + vc] : 0.f;
        }
        __syncthreads();
        for (int pp = 0; pp < cnt; pp++) {
            const float rv = Vs[pp][d];
            acc[0] += aggs[lg4][p0 + pp] * rv;
            acc[1] += aggs[lg4 + 4][p0 + pp] * rv;
            acc[2] += aggs[lg4 + 8][p0 + pp] * rv;
            acc[3] += aggs[lg4 + 12][p0 + pp] * rv;
        }
        __syncthreads();
    }

#pragma unroll
    for (int i = 0; i < 4; i++) {
        const int lg = l0 + lg4 + 4 * i;
        ctx[(((size_t)(b << 10) + lg) << 10) + (h << 6) + d] = acc[i];
    }
}

// ---------------------------------------------------------------------------
extern "C" void kernel_launch(void* const* d_in, const int* in_sizes, int n_in,
                              void* d_out, int out_size) {
    const float* query = (const float*)d_in[0];
    const float* key_  = (const float*)d_in[1];
    const float* value = (const float*)d_in[2];
    const float* w_q   = (const float*)d_in[3];
    const float* w_k   = (const float*)d_in[4];
    const float* w_v   = (const float*)d_in[5];
    const float* w_o   = (const float*)d_in[6];
    const float* b_o   = (const float*)d_in[7];
    const float* rel_k = (const float*)d_in[8];
    const float* rel_v = (const float*)d_in[9];
    const float* decay = (const float*)d_in[10];

    float* out  = (float*)d_out;
    float* attn = out + (size_t)MTOT * DMODEL;

    float *Q, *K, *V, *Qrel, *ctx;
    __nv_bfloat16 *Ah, *Al, *Wh, *Wl;
    cudaGetSymbolAddress((void**)&Q,    g_Q);
    cudaGetSymbolAddress((void**)&K,    g_K);
    cudaGetSymbolAddress((void**)&V,    g_V);
    cudaGetSymbolAddress((void**)&Qrel, g_Qrel);
    cudaGetSymbolAddress((void**)&ctx,  g_ctx);
    cudaGetSymbolAddress((void**)&Ah,   g_Ah);
    cudaGetSymbolAddress((void**)&Al,   g_Al);
    cudaGetSymbolAddress((void**)&Wh,   g_Wh);
    cudaGetSymbolAddress((void**)&Wl,   g_Wl);

    cudaFuncSetAttribute(gemm_mma<0>, cudaFuncAttributeMaxDynamicSharedMemorySize, GEMM_SMEM);
    cudaFuncSetAttribute(gemm_mma<1>, cudaFuncAttributeMaxDynamicSharedMemorySize, GEMM_SMEM);

    const int nA4 = MTOT * DMODEL / 4;
    const int nW4 = DMODEL * DMODEL / 4;
    const dim3 ggemm(DMODEL / 128, MTOT / 128);   // (8, 64)

    cvt_split<<<nA4 / 256, 256>>>((const float4*)query, (uint2*)Ah, (uint2*)Al);
    cvt_split<<<nW4 / 256, 256>>>((const float4*)w_q, (uint2*)Wh, (uint2*)Wl);
    gemm_mma<0><<<ggemm, 256, GEMM_SMEM>>>(Ah, Al, Wh, Wl, nullptr, Q);

    cvt_split<<<nA4 / 256, 256>>>((const float4*)key_, (uint2*)Ah, (uint2*)Al);
    cvt_split<<<nW4 / 256, 256>>>((const float4*)w_k, (uint2*)Wh, (uint2*)Wl);
    gemm_mma<0><<<ggemm, 256, GEMM_SMEM>>>(Ah, Al, Wh, Wl, nullptr, K);

    cvt_split<<<nA4 / 256, 256>>>((const float4*)value, (uint2*)Ah, (uint2*)Al);
    cvt_split<<<nW4 / 256, 256>>>((const float4*)w_v, (uint2*)Wh, (uint2*)Wl);
    gemm_mma<0><<<ggemm, 256, GEMM_SMEM>>>(Ah, Al, Wh, Wl, nullptr, V);

    qrel_kernel<<<dim3(5, 16, BH), 256>>>(Q, rel_k, Qrel);

    static const size_t attn_smem = ATTN_SMEM_FLOATS * sizeof(float);
    cudaFuncSetAttribute(attn_kernel, cudaFuncAttributeMaxDynamicSharedMemorySize,
                         (int)attn_smem);
    attn_kernel<<<dim3(SEQ / 16, BH), 256, attn_smem>>>(Q, K, Qrel, decay, attn);

    ctx_kernel<<<dim3(SEQ / 16, BH), 256>>>(attn, V, rel_v, ctx);

    cvt_split<<<nA4 / 256, 256>>>((const float4*)ctx, (uint2*)Ah, (uint2*)Al);
    cvt_split<<<nW4 / 256, 256>>>((const float4*)w_o, (uint2*)Wh, (uint2*)Wl);
    gemm_mma<1><<<ggemm, 256, GEMM_SMEM>>>(Ah, Al, Wh, Wl, b_o, out);
}